// round 17
// baseline (speedup 1.0000x reference)
#include <cuda_runtime.h>
#include <cuda_bf16.h>
#include <cstdint>

#define BTOK  65536
#define HID   512
#define DIN   512
#define NEXP  64
#define FOURE 256
#define TAU   2e-5f

typedef __nv_bfloat16 bf16;
typedef unsigned int u32;

// ---------------- scratch (static __device__, no allocation) ----------------
__device__ __align__(16) bf16 g_qfh[(size_t)BTOK * DIN];
__device__ __align__(16) bf16 g_qfl[(size_t)BTOK * DIN];
__device__ __align__(16) bf16 g_mmh[(size_t)BTOK * HID];
__device__ __align__(16) bf16 g_mml[(size_t)BTOK * HID];
__device__ __align__(16) bf16 g_x1h[(size_t)BTOK * HID];
__device__ __align__(16) bf16 g_x1l[(size_t)BTOK * HID];
__device__ __align__(16) bf16 g_x2h[(size_t)BTOK * HID];
__device__ __align__(16) bf16 g_x2l[(size_t)BTOK * HID];
__device__ __align__(16) bf16 g_x3h[(size_t)BTOK * HID];
__device__ __align__(16) bf16 g_x3l[(size_t)BTOK * HID];
__device__ __align__(16) bf16 g_x4h[(size_t)BTOK * FOURE];
__device__ __align__(16) bf16 g_x4l[(size_t)BTOK * FOURE];
__device__ __align__(16) bf16 g_w1h[(size_t)HID * DIN];
__device__ __align__(16) bf16 g_w1l[(size_t)HID * DIN];
__device__ __align__(16) bf16 g_w2h[(size_t)HID * HID];
__device__ __align__(16) bf16 g_w2l[(size_t)HID * HID];
__device__ __align__(16) bf16 g_wfh[(size_t)HID * 2 * HID];
__device__ __align__(16) bf16 g_wfl[(size_t)HID * 2 * HID];
__device__ __align__(16) bf16 g_g1h[(size_t)FOURE * HID];
__device__ __align__(16) bf16 g_g1l[(size_t)FOURE * HID];
__device__ __align__(16) bf16 g_g2h[(size_t)NEXP * FOURE];
__device__ __align__(16) bf16 g_g2l[(size_t)NEXP * FOURE];
__device__ float g_l[(size_t)BTOK * NEXP];
__device__ int   g_list[BTOK];
__device__ int   g_count;

// ---------------- helpers ----------------------------------------------------
__device__ __forceinline__ u32 smem_u32(const void* p) {
    u32 a;
    asm("{ .reg .u64 t; cvta.to.shared.u64 t, %1; cvt.u32.u64 %0, t; }" : "=r"(a) : "l"(p));
    return a;
}
// swizzled byte offset inside a [rows][32 bf16] tile (row stride 64B).
__device__ __forceinline__ int swoff(int r, int c8) {
    return r * 64 + ((((c8 >> 3) ^ ((r >> 1) & 3)) & 3) << 4);
}
__device__ __forceinline__ void ldsm4(u32* r, u32 a) {
    asm volatile("ldmatrix.sync.aligned.m8n8.x4.shared.b16 {%0,%1,%2,%3}, [%4];"
                 : "=r"(r[0]), "=r"(r[1]), "=r"(r[2]), "=r"(r[3]) : "r"(a));
}
__device__ __forceinline__ void hmma(float* d, const u32* a, u32 b0, u32 b1) {
    asm volatile(
        "mma.sync.aligned.m16n8k16.row.col.f32.bf16.bf16.f32 "
        "{%0,%1,%2,%3}, {%4,%5,%6,%7}, {%8,%9}, {%0,%1,%2,%3};"
        : "+f"(d[0]), "+f"(d[1]), "+f"(d[2]), "+f"(d[3])
        : "r"(a[0]), "r"(a[1]), "r"(a[2]), "r"(a[3]), "r"(b0), "r"(b1));
}

// ---------------- split fp32 -> hi/lo bf16 -----------------------------------
__global__ void split2(const float* __restrict__ x, bf16* __restrict__ h,
                       bf16* __restrict__ l, int n)
{
    int i = blockIdx.x * blockDim.x + threadIdx.x;
    if (i >= n) return;
    float v = x[i];
    bf16 a = __float2bfloat16(v);
    h[i] = a;
    l[i] = __float2bfloat16(v - __bfloat162float(a));
}

__global__ void zero_cnt() { g_count = 0; }

// ---------------- HMMA bf16x2-split layer (double-buffered) ------------------
// CTA 128 x (64*NBLK); 8 warps, warp tile 32 x (32*NBLK). K tiles of 32,
// 3 split-products per k16 in fixed order (kt asc, kh asc) -> per-output
// accumulation order identical for all NBLK => logits bit-stable.
struct LArgs {
    const bf16 *a0h, *a0l, *a1h, *a1l;
    const bf16 *bh, *bl;
    const float* bias;
    bf16 *oh, *ol;
    float* of;
    int K0, K, N, act, outf;
};

#define LDG_T(kt)                                                             \
    {                                                                         \
        const bool s0 = (kt) < ar.K0;                                         \
        const int stride = s0 ? ar.K0 : (ar.K - ar.K0);                       \
        const int goff = s0 ? (kt) : ((kt) - ar.K0);                          \
        const bf16* ah = s0 ? ar.a0h : ar.a1h;                                \
        const bf16* al = s0 ? ar.a0l : ar.a1l;                                \
        _Pragma("unroll")                                                     \
        for (int c = 0; c < 2; c++) {                                         \
            int fidx = c * 256 + tid, r = fidx >> 2, c8 = (fidx & 3) * 8;     \
            const size_t go = (size_t)(m0 + r) * stride + goff + c8;          \
            rAh[c] = *(const uint4*)(ah + go);                                \
            rAl[c] = *(const uint4*)(al + go);                                \
        }                                                                     \
        _Pragma("unroll")                                                     \
        for (int c = 0; c < NBLK; c++) {                                      \
            int fidx = c * 256 + tid, r = fidx >> 2, c8 = (fidx & 3) * 8;     \
            const size_t go = (size_t)(n0 + r) * ar.K + (kt) + c8;            \
            rBh[c] = *(const uint4*)(ar.bh + go);                             \
            rBl[c] = *(const uint4*)(ar.bl + go);                             \
        }                                                                     \
    }

#define STS_T(buf)                                                            \
    {                                                                         \
        _Pragma("unroll")                                                     \
        for (int c = 0; c < 2; c++) {                                         \
            int fidx = c * 256 + tid, r = fidx >> 2, c8 = (fidx & 3) * 8;     \
            *(uint4*)((char*)As[buf][0] + swoff(r, c8)) = rAh[c];             \
            *(uint4*)((char*)As[buf][1] + swoff(r, c8)) = rAl[c];             \
        }                                                                     \
        _Pragma("unroll")                                                     \
        for (int c = 0; c < NBLK; c++) {                                      \
            int fidx = c * 256 + tid, r = fidx >> 2, c8 = (fidx & 3) * 8;     \
            *(uint4*)((char*)Bs[buf][0] + swoff(r, c8)) = rBh[c];             \
            *(uint4*)((char*)Bs[buf][1] + swoff(r, c8)) = rBl[c];             \
        }                                                                     \
    }

template <int NBLK>
__global__ void __launch_bounds__(256, NBLK == 1 ? 2 : 1) mma_layer(LArgs ar)
{
    __shared__ __align__(16) bf16 As[2][2][128 * 32];
    __shared__ __align__(16) bf16 Bs[2][2][64 * NBLK * 32];
    const int tid = threadIdx.x, wid = tid >> 5, lane = tid & 31;
    const int m0 = blockIdx.y * 128, n0 = blockIdx.x * (64 * NBLK);
    const int mbase = (wid & 3) * 32, nbase = (wid >> 2) * (32 * NBLK);

    float acc[2][4 * NBLK][4];
#pragma unroll
    for (int i = 0; i < 2; i++)
#pragma unroll
        for (int j = 0; j < 4 * NBLK; j++)
#pragma unroll
            for (int c = 0; c < 4; c++) acc[i][j][c] = 0.f;

    uint4 rAh[2], rAl[2], rBh[NBLK], rBl[NBLK];

    LDG_T(0);
    STS_T(0);
    __syncthreads();

    int p = 0;
    for (int kt = 0; kt < ar.K; kt += 32) {
        const bool nxt = (kt + 32) < ar.K;
        if (nxt) LDG_T(kt + 32);

        const u32 asb0 = smem_u32(As[p][0]), asb1 = smem_u32(As[p][1]);
        const u32 bsb0 = smem_u32(Bs[p][0]), bsb1 = smem_u32(Bs[p][1]);
#pragma unroll
        for (int kh = 0; kh < 32; kh += 16) {
            u32 a[2][2][4], b[2][2 * NBLK][4];
            {
                const int rr = (lane & 7) + ((lane >> 3) & 1) * 8;
                const int c8 = kh + (lane >> 4) * 8;
#pragma unroll
                for (int i = 0; i < 2; i++) {
                    const int off = swoff(mbase + i * 16 + rr, c8);
                    ldsm4(a[0][i], asb0 + off);
                    ldsm4(a[1][i], asb1 + off);
                }
            }
            {
                const int mi = lane >> 3;
#pragma unroll
                for (int pb = 0; pb < 2 * NBLK; pb++) {
                    const int row = nbase + (pb * 2 + (mi >> 1)) * 8 + (lane & 7);
                    const int c8 = kh + (mi & 1) * 8;
                    const int off = swoff(row, c8);
                    ldsm4(b[0][pb], bsb0 + off);
                    ldsm4(b[1][pb], bsb1 + off);
                }
            }
#pragma unroll
            for (int pr = 0; pr < 3; pr++) {
                const int sa = (pr == 2) ? 1 : 0;
                const int sb = (pr == 1) ? 1 : 0;
#pragma unroll
                for (int i = 0; i < 2; i++)
#pragma unroll
                    for (int j = 0; j < 4 * NBLK; j++) {
                        const int pb = j >> 1, ix = (j & 1) * 2;
                        hmma(acc[i][j], a[sa][i], b[sb][pb][ix], b[sb][pb][ix + 1]);
                    }
            }
        }

        if (nxt) {
            STS_T(p ^ 1);
            __syncthreads();
        }
        p ^= 1;
    }

    // epilogue: bias + act, write hi/lo splits (or f32 for logits)
    const int g = lane >> 2, t = lane & 3;
#pragma unroll
    for (int i = 0; i < 2; i++)
#pragma unroll
        for (int j = 0; j < 4 * NBLK; j++) {
            const int col = n0 + nbase + j * 8 + 2 * t;
            const float bb0 = ar.bias ? ar.bias[col] : 0.f;
            const float bb1 = ar.bias ? ar.bias[col + 1] : 0.f;
#pragma unroll
            for (int h = 0; h < 2; h++) {
                const int R = m0 + mbase + i * 16 + g + h * 8;
                float v0 = acc[i][j][h * 2 + 0] + bb0;
                float v1 = acc[i][j][h * 2 + 1] + bb1;
                if (ar.act == 1)      { v0 = fmaxf(v0, 0.f); v1 = fmaxf(v1, 0.f); }
                else if (ar.act == 2) { v0 = tanhf(v0);      v1 = tanhf(v1); }
                const size_t o = (size_t)R * ar.N + col;
                if (ar.outf) {
                    *(float2*)(ar.of + o) = make_float2(v0, v1);
                } else {
                    bf16 h0 = __float2bfloat16(v0), h1 = __float2bfloat16(v1);
                    __nv_bfloat162 hv; hv.x = h0; hv.y = h1;
                    *(__nv_bfloat162*)(ar.oh + o) = hv;
                    __nv_bfloat162 lv;
                    lv.x = __float2bfloat16(v0 - __bfloat162float(h0));
                    lv.y = __float2bfloat16(v1 - __bfloat162float(h1));
                    *(__nv_bfloat162*)(ar.ol + o) = lv;
                }
            }
        }
}

// ---------------- warp softmax/top2 ------------------------------------------
__device__ __forceinline__ void top2_write(float l0, float l1, int lane, int b,
                                           float* out, int out_size, bool flag_mode)
{
    const int OFF_L = BTOK * NEXP, OFF_W = 2 * BTOK * NEXP, OFF_I = 3 * BTOK * NEXP;
    const bool wl = out_size >= OFF_W, ww = out_size >= OFF_I;
    const bool wi = out_size >= OFF_I + 2 * BTOK;

    float m = fmaxf(l0, l1);
#pragma unroll
    for (int o = 16; o; o >>= 1) m = fmaxf(m, __shfl_xor_sync(0xffffffffu, m, o));
    float e0 = expf(l0 - m), e1 = expf(l1 - m);
    float sd = e0 + e1;
#pragma unroll
    for (int o = 16; o; o >>= 1) sd += __shfl_xor_sync(0xffffffffu, sd, o);
    float w0 = e0 / sd, w1 = e1 / sd;

    float bv; int bi;
    if (w0 >= w1) { bv = w0; bi = lane; } else { bv = w1; bi = lane + 32; }
#pragma unroll
    for (int o = 16; o; o >>= 1) {
        float ov = __shfl_xor_sync(0xffffffffu, bv, o);
        int oi = __shfl_xor_sync(0xffffffffu, bi, o);
        if (ov > bv || (ov == bv && oi < bi)) { bv = ov; bi = oi; }
    }
    float d0 = (lane == bi) ? -1.f : w0;
    float d1 = (lane + 32 == bi) ? -1.f : w1;
    float bv2; int bi2;
    if (d0 >= d1) { bv2 = d0; bi2 = lane; } else { bv2 = d1; bi2 = lane + 32; }
#pragma unroll
    for (int o = 16; o; o >>= 1) {
        float ov = __shfl_xor_sync(0xffffffffu, bv2, o);
        int oi = __shfl_xor_sync(0xffffffffu, bi2, o);
        if (ov > bv2 || (ov == bv2 && oi < bi2)) { bv2 = ov; bi2 = oi; }
    }
    if (flag_mode) {
        float f0 = (lane == bi || lane == bi2) ? -1.f : w0;
        float f1 = (lane + 32 == bi || lane + 32 == bi2) ? -1.f : w1;
        float bv3 = fmaxf(f0, f1);
#pragma unroll
        for (int o = 16; o; o >>= 1) bv3 = fmaxf(bv3, __shfl_xor_sync(0xffffffffu, bv3, o));
        if (lane == 0 && (bv - bv2 < TAU || bv2 - bv3 < TAU)) {
            int p = atomicAdd(&g_count, 1);
            if (p < BTOK) g_list[p] = b;
        }
    }
    const float den = bv + bv2 + 1e-6f;
    const float r1 = bv / den, r2 = bv2 / den;
    const size_t base = (size_t)b * NEXP;
    out[base + lane]      = (lane == bi) ? r1 : (lane == bi2) ? r2 : 0.f;
    out[base + lane + 32] = (lane + 32 == bi) ? r1 : (lane + 32 == bi2) ? r2 : 0.f;
    if (wl) { out[OFF_L + base + lane] = l0; out[OFF_L + base + lane + 32] = l1; }
    if (ww) { out[OFF_W + base + lane] = w0; out[OFF_W + base + lane + 32] = w1; }
    if (wi && lane == 0) {
        out[OFF_I + (size_t)b * 2]     = (float)bi;
        out[OFF_I + (size_t)b * 2 + 1] = (float)bi2;
    }
}

__global__ __launch_bounds__(256) void epilogue_kernel(float* __restrict__ out, int out_size)
{
    const int lane = threadIdx.x & 31;
    const int b = blockIdx.x * 8 + (threadIdx.x >> 5);
    const size_t base = (size_t)b * NEXP;
    top2_write(g_l[base + lane], g_l[base + lane + 32], lane, b, out, out_size, true);
}

// ---------------- exact path: warp-cooperative Kahan recompute ---------------
__device__ __forceinline__ void wdot2(const float* __restrict__ x,
                                      const float* __restrict__ w0,
                                      const float* __restrict__ w1,
                                      int K, int lane, float& r0, float& r1)
{
    float s0 = 0.f, c0 = 0.f, s1 = 0.f, c1 = 0.f;
    for (int k = lane; k < K; k += 32) {
        const float xv = x[k];
        { float y = fmaf(xv, w0[k], -c0); float t = s0 + y; c0 = (t - s0) - y; s0 = t; }
        { float y = fmaf(xv, w1[k], -c1); float t = s1 + y; c1 = (t - s1) - y; s1 = t; }
    }
    s0 -= c0; s1 -= c1;
#pragma unroll
    for (int o = 16; o; o >>= 1) {
        s0 += __shfl_xor_sync(0xffffffffu, s0, o);
        s1 += __shfl_xor_sync(0xffffffffu, s1, o);
    }
    r0 = s0; r1 = s1;
}

__global__ __launch_bounds__(256) void exact_fix(
    const float* mm, const float* qf,
    const float* W1, const float* b1, const float* W2, const float* b2,
    const float* Wf, const float* bfu, const float* Wg1, const float* Wg2,
    float* out, int out_size)
{
    __shared__ float sA[8][1024];
    __shared__ float sB[8][512];
    const int wid = threadIdx.x >> 5, lane = threadIdx.x & 31;
    const int cnt = g_count;
    for (int base = blockIdx.x * 8; base < cnt; base += gridDim.x * 8) {
        const int idx = base + wid;
        if (idx < cnt) {
            const int b = g_list[idx];
            float* xa = sA[wid];
            float* xb = sB[wid];
            for (int k = lane; k < DIN; k += 32) xa[k] = qf[(size_t)b * DIN + k];
            __syncwarp();
            for (int n = 0; n < HID; n += 2) {
                float d0, d1;
                wdot2(xa, W1 + (size_t)n * DIN, W1 + (size_t)(n + 1) * DIN, DIN, lane, d0, d1);
                if (lane == 0) {
                    xb[n] = fmaxf(d0 + b1[n], 0.f);
                    xb[n + 1] = fmaxf(d1 + b1[n + 1], 0.f);
                }
            }
            __syncwarp();
            for (int n = 0; n < HID; n += 2) {
                float d0, d1;
                wdot2(xb, W2 + (size_t)n * HID, W2 + (size_t)(n + 1) * HID, HID, lane, d0, d1);
                if (lane == 0) { xa[HID + n] = d0 + b2[n]; xa[HID + n + 1] = d1 + b2[n + 1]; }
            }
            __syncwarp();
            for (int k = lane; k < HID; k += 32) xa[k] = mm[(size_t)b * HID + k];
            __syncwarp();
            for (int n = 0; n < HID; n += 2) {
                float d0, d1;
                wdot2(xa, Wf + (size_t)n * 2 * HID, Wf + (size_t)(n + 1) * 2 * HID, 2 * HID, lane, d0, d1);
                if (lane == 0) {
                    xb[n] = fmaxf(d0 + bfu[n], 0.f);
                    xb[n + 1] = fmaxf(d1 + bfu[n + 1], 0.f);
                }
            }
            __syncwarp();
            for (int n = 0; n < FOURE; n += 2) {
                float d0, d1;
                wdot2(xb, Wg1 + (size_t)n * HID, Wg1 + (size_t)(n + 1) * HID, HID, lane, d0, d1);
                if (lane == 0) { xa[n] = tanhf(d0); xa[n + 1] = tanhf(d1); }
            }
            __syncwarp();
            for (int n = 0; n < NEXP; n += 2) {
                float d0, d1;
                wdot2(xa, Wg2 + (size_t)n * FOURE, Wg2 + (size_t)(n + 1) * FOURE, FOURE, lane, d0, d1);
                if (lane == 0) { xb[n] = d0; xb[n + 1] = d1; }
            }
            __syncwarp();
            top2_write(xb[lane], xb[lane + 32], lane, b, out, out_size, false);
        }
    }
}

// ---------------- launch -----------------------------------------------------
extern "C" void kernel_launch(void* const* d_in, const int* in_sizes, int n_in,
                              void* d_out, int out_size)
{
    const float* mm    = (const float*)d_in[0];
    const float* qf    = (const float*)d_in[1];
    const float* W_qe1 = (const float*)d_in[2];
    const float* b_qe1 = (const float*)d_in[3];
    const float* W_qe2 = (const float*)d_in[4];
    const float* b_qe2 = (const float*)d_in[5];
    const float* W_fus = (const float*)d_in[6];
    const float* b_fus = (const float*)d_in[7];
    const float* W_g1  = (const float*)d_in[8];
    const float* W_g2  = (const float*)d_in[9];
    float* out = (float*)d_out;

    bf16 *qfh, *qfl, *mmh, *mml, *x1h, *x1l, *x2h, *x2l, *x3h, *x3l, *x4h, *x4l;
    bf16 *w1h, *w1l, *w2h, *w2l, *wfh, *wfl, *g1h, *g1l, *g2h, *g2l;
    float* pl;
    cudaGetSymbolAddress((void**)&qfh, g_qfh); cudaGetSymbolAddress((void**)&qfl, g_qfl);
    cudaGetSymbolAddress((void**)&mmh, g_mmh); cudaGetSymbolAddress((void**)&mml, g_mml);
    cudaGetSymbolAddress((void**)&x1h, g_x1h); cudaGetSymbolAddress((void**)&x1l, g_x1l);
    cudaGetSymbolAddress((void**)&x2h, g_x2h); cudaGetSymbolAddress((void**)&x2l, g_x2l);
    cudaGetSymbolAddress((void**)&x3h, g_x3h); cudaGetSymbolAddress((void**)&x3l, g_x3l);
    cudaGetSymbolAddress((void**)&x4h, g_x4h); cudaGetSymbolAddress((void**)&x4l, g_x4l);
    cudaGetSymbolAddress((void**)&w1h, g_w1h); cudaGetSymbolAddress((void**)&w1l, g_w1l);
    cudaGetSymbolAddress((void**)&w2h, g_w2h); cudaGetSymbolAddress((void**)&w2l, g_w2l);
    cudaGetSymbolAddress((void**)&wfh, g_wfh); cudaGetSymbolAddress((void**)&wfl, g_wfl);
    cudaGetSymbolAddress((void**)&g1h, g_g1h); cudaGetSymbolAddress((void**)&g1l, g_g1l);
    cudaGetSymbolAddress((void**)&g2h, g_g2h); cudaGetSymbolAddress((void**)&g2l, g_g2l);
    cudaGetSymbolAddress((void**)&pl, g_l);

    zero_cnt<<<1, 1>>>();

    const int NA = BTOK * DIN;
    split2<<<(NA + 255) / 256, 256>>>(qf, qfh, qfl, NA);
    split2<<<(NA + 255) / 256, 256>>>(mm, mmh, mml, NA);
    split2<<<(HID * DIN + 255) / 256, 256>>>(W_qe1, w1h, w1l, HID * DIN);
    split2<<<(HID * HID + 255) / 256, 256>>>(W_qe2, w2h, w2l, HID * HID);
    split2<<<(HID * 2 * HID + 255) / 256, 256>>>(W_fus, wfh, wfl, HID * 2 * HID);
    split2<<<(FOURE * HID + 255) / 256, 256>>>(W_g1, g1h, g1l, FOURE * HID);
    split2<<<(NEXP * FOURE + 255) / 256, 256>>>(W_g2, g2h, g2l, NEXP * FOURE);

    const dim3 blk(256);
    LArgs a;
    // L1: x1 = relu(qf @ W1^T + b1)   N=512, NBLK=2 -> CTA 128x128
    a = LArgs{qfh, qfl, nullptr, nullptr, w1h, w1l, b_qe1,
              x1h, x1l, nullptr, DIN, DIN, HID, 1, 0};
    mma_layer<2><<<dim3(HID / 128, BTOK / 128), blk>>>(a);
    // L2: x2 = x1 @ W2^T + b2         N=512
    a = LArgs{x1h, x1l, nullptr, nullptr, w2h, w2l, b_qe2,
              x2h, x2l, nullptr, HID, HID, HID, 0, 0};
    mma_layer<2><<<dim3(HID / 128, BTOK / 128), blk>>>(a);
    // L3: x3 = relu([mm | x2] @ Wf^T + bf)  N=512, K=1024
    a = LArgs{mmh, mml, x2h, x2l, wfh, wfl, b_fus,
              x3h, x3l, nullptr, HID, 2 * HID, HID, 1, 0};
    mma_layer<2><<<dim3(HID / 128, BTOK / 128), blk>>>(a);
    // L4: x4 = tanh(x3 @ Wg1^T)       N=256
    a = LArgs{x3h, x3l, nullptr, nullptr, g1h, g1l, nullptr,
              x4h, x4l, nullptr, HID, HID, FOURE, 2, 0};
    mma_layer<2><<<dim3(FOURE / 128, BTOK / 128), blk>>>(a);
    // L5: logits = x4 @ Wg2^T (fp32 out)  N=64, NBLK=1
    a = LArgs{x4h, x4l, nullptr, nullptr, g2h, g2l, nullptr,
              nullptr, nullptr, pl, FOURE, FOURE, NEXP, 0, 1};
    mma_layer<1><<<dim3(NEXP / 64, BTOK / 128), blk>>>(a);

    epilogue_kernel<<<BTOK / 8, 256>>>(out, out_size);
    exact_fix<<<256, 256>>>(mm, qf, W_qe1, b_qe1, W_qe2, b_qe2,
                            W_fus, b_fus, W_g1, W_g2, out, out_size);
}